// round 1
// baseline (speedup 1.0000x reference)
#include <cuda_runtime.h>
#include <math.h>

// Problem constants
#define BSZ   64
#define TT    256
#define IND   64
#define HD    768
#define G4    3072      // 4*H
#define NCTA  128       // persistent grid size (<= 148 SMs -> all co-resident)
#define LUD   256

// Scratch (static device allocations are the sanctioned workaround)
__device__ __align__(16) float g_XG[(size_t)TT * G4 * BSZ];   // [t][gatecol][b]      ~201 MB
__device__ __align__(16) float g_H1[(size_t)TT * HD * BSZ];   // [t][k>>2][b][k&3]    ~50 MB
__device__ __align__(16) float g_H2[2 * HD * BSZ];            // double buffer, same interleave
__device__ unsigned long long g_bar = 0;                      // cumulative barrier counter

// ---------------------------------------------------------------------------
// Software grid barrier: cumulative-ticket scheme, safe across graph replays
// (counter only ever increases; "need" is computed from the returned ticket).
// __threadfence() is gpu-scope => ptxas emits CCTL.IVALL, flushing L1 so
// cross-CTA h reads after the barrier are never stale.
// ---------------------------------------------------------------------------
__device__ __forceinline__ void grid_barrier()
{
    __threadfence();          // release this thread's h/c stores
    __syncthreads();          // all block threads fenced before arrival
    if (threadIdx.x == 0) {
        unsigned long long ticket = atomicAdd(&g_bar, 1ULL) + 1ULL;
        unsigned long long need = ((ticket + (NCTA - 1)) / NCTA) * NCTA;
        volatile unsigned long long* p = &g_bar;
        while (*p < need) { __nanosleep(40); }
    }
    __syncthreads();
    __threadfence();          // acquire + L1 invalidate before reading peers' h
}

__device__ __forceinline__ float sigmoidf_(float x)
{
    return 1.0f / (1.0f + __expf(-x));
}

// ---------------------------------------------------------------------------
// proj0: g_XG[t][c][b] = sum_d (x[b][t][d]/1.5) * Wih0[c][d] + bih0[c] + bhh0[c]
// Block: 256 threads handles (t, 64-col tile) over all 64 batches.
// ---------------------------------------------------------------------------
__global__ void proj0_kernel(const float* __restrict__ x,
                             const float* __restrict__ Wih0,
                             const float* __restrict__ bih0,
                             const float* __restrict__ bhh0)
{
    __shared__ float4 Xs4[64 * 17];   // [b][d4], padded stride 17 float4
    __shared__ float4 Ws4[64 * 17];   // [c][d4]
    float* Xs = (float*)Xs4;
    float* Ws = (float*)Ws4;

    const int t   = blockIdx.y;
    const int c0  = blockIdx.x * 64;
    const int tid = threadIdx.x;
    const float inv = 1.0f / 1.5f;

    for (int idx = tid; idx < 64 * 64; idx += 256) {
        int b = idx >> 6, d = idx & 63;
        Xs[b * 68 + d] = x[((b * TT) + t) * IND + d] * inv;
    }
    for (int idx = tid; idx < 64 * 64; idx += 256) {
        int c = idx >> 6, d = idx & 63;
        Ws[c * 68 + d] = Wih0[(c0 + c) * IND + d];
    }
    __syncthreads();

    const int b  = tid & 63;
    const int cw = tid >> 6;              // 0..3  (cols cw + 4*m)

    float acc[16];
#pragma unroll
    for (int m = 0; m < 16; m++) acc[m] = 0.0f;

#pragma unroll
    for (int d4 = 0; d4 < 16; d4++) {
        float4 xv = Xs4[b * 17 + d4];
#pragma unroll
        for (int m = 0; m < 16; m++) {
            float4 wv = Ws4[(cw + 4 * m) * 17 + d4];
            acc[m] += xv.x * wv.x + xv.y * wv.y + xv.z * wv.z + xv.w * wv.w;
        }
    }
#pragma unroll
    for (int m = 0; m < 16; m++) {
        int c = c0 + cw + 4 * m;
        float v = acc[m] + bih0[c] + bhh0[c];
        g_XG[((size_t)t * G4 + c) * 64 + b] = v;   // warp: consecutive b -> coalesced
    }
}

// ---------------------------------------------------------------------------
// lstm0: persistent recurrence for layer 0.
// CTA owns h-cols j = blockIdx.x*6 .. +5 ; thread = (jl, b).
// Whh slice in shared as float4 per (k, jl): components = gates {i,f,g,o}.
// ---------------------------------------------------------------------------
__global__ void __launch_bounds__(384, 1)
lstm0_kernel(const float* __restrict__ Whh0)
{
    extern __shared__ float4 Wsh[];     // 768*6 float4 = 73728 B
    float* Wsf = (float*)Wsh;

    const int tid = threadIdx.x;
    const int jl  = tid / 64;           // 0..5
    const int b   = tid & 63;
    const int j   = blockIdx.x * 6 + jl;

    // Stage weights: Wsf[k*24 + jj*4 + gi] = Whh0[(gi*768 + base_j + jj)][k]
    for (int idx = tid; idx < 768 * 24; idx += 384) {
        int k  = idx / 24;
        int r  = idx % 24;
        int jj = r >> 2;
        int gi = r & 3;
        Wsf[idx] = Whh0[(gi * 768 + blockIdx.x * 6 + jj) * 768 + k];
    }
    __syncthreads();

    float c = 0.0f;
    for (int t = 0; t < TT; t++) {
        int base = (t * G4 + j) * 64 + b;
        float ai = g_XG[base];
        float af = g_XG[base + 768 * 64];
        float ag = g_XG[base + 1536 * 64];
        float ao = g_XG[base + 2304 * 64];

        if (t > 0) {
            const float4* h4 = (const float4*)(g_H1 + (size_t)(t - 1) * (HD * 64));
#pragma unroll 4
            for (int k4 = 0; k4 < 192; k4++) {
                float4 hv = h4[k4 * 64 + b];
                float4 w0 = Wsh[(k4 * 4 + 0) * 6 + jl];
                float4 w1 = Wsh[(k4 * 4 + 1) * 6 + jl];
                float4 w2 = Wsh[(k4 * 4 + 2) * 6 + jl];
                float4 w3 = Wsh[(k4 * 4 + 3) * 6 + jl];
                ai += hv.x * w0.x + hv.y * w1.x + hv.z * w2.x + hv.w * w3.x;
                af += hv.x * w0.y + hv.y * w1.y + hv.z * w2.y + hv.w * w3.y;
                ag += hv.x * w0.z + hv.y * w1.z + hv.z * w2.z + hv.w * w3.z;
                ao += hv.x * w0.w + hv.y * w1.w + hv.z * w2.w + hv.w * w3.w;
            }
        }
        float ig = sigmoidf_(ai);
        float fg = sigmoidf_(af);
        float gg = tanhf(ag);
        float og = sigmoidf_(ao);
        c = fg * c + ig * gg;
        float h = og * tanhf(c);

        g_H1[(size_t)t * (HD * 64) + (size_t)(((j >> 2) * 64 + b) * 4 + (j & 3))] = h;
        grid_barrier();
    }
}

// ---------------------------------------------------------------------------
// lstm1: persistent layer-1, input projection fused per step (K = 1536).
// Shared holds Wih1 slice (first 768 k) and Whh1 slice (next 768 k).
// ---------------------------------------------------------------------------
__global__ void __launch_bounds__(384, 1)
lstm1_kernel(const float* __restrict__ Wih1, const float* __restrict__ Whh1,
             const float* __restrict__ bih1, const float* __restrict__ bhh1)
{
    extern __shared__ float4 Wsh[];     // 1536*6 float4 = 147456 B
    float* Wsf = (float*)Wsh;

    const int tid = threadIdx.x;
    const int jl  = tid / 64;
    const int b   = tid & 63;
    const int j   = blockIdx.x * 6 + jl;

    for (int idx = tid; idx < 768 * 24; idx += 384) {
        int k  = idx / 24;
        int r  = idx % 24;
        int jj = r >> 2;
        int gi = r & 3;
        int row = (gi * 768 + blockIdx.x * 6 + jj) * 768 + k;
        Wsf[idx]            = Wih1[row];
        Wsf[768 * 24 + idx] = Whh1[row];
    }
    __syncthreads();

    float bi = bih1[j]          + bhh1[j];
    float bf = bih1[768 + j]    + bhh1[768 + j];
    float bg = bih1[1536 + j]   + bhh1[1536 + j];
    float bo = bih1[2304 + j]   + bhh1[2304 + j];

    float c = 0.0f;
    for (int t = 0; t < TT; t++) {
        float ai = bi, af = bf, ag = bg, ao = bo;

        // input part: h1[t] . Wih1
        const float4* h1p = (const float4*)(g_H1 + (size_t)t * (HD * 64));
#pragma unroll 4
        for (int k4 = 0; k4 < 192; k4++) {
            float4 hv = h1p[k4 * 64 + b];
            float4 w0 = Wsh[(k4 * 4 + 0) * 6 + jl];
            float4 w1 = Wsh[(k4 * 4 + 1) * 6 + jl];
            float4 w2 = Wsh[(k4 * 4 + 2) * 6 + jl];
            float4 w3 = Wsh[(k4 * 4 + 3) * 6 + jl];
            ai += hv.x * w0.x + hv.y * w1.x + hv.z * w2.x + hv.w * w3.x;
            af += hv.x * w0.y + hv.y * w1.y + hv.z * w2.y + hv.w * w3.y;
            ag += hv.x * w0.z + hv.y * w1.z + hv.z * w2.z + hv.w * w3.z;
            ao += hv.x * w0.w + hv.y * w1.w + hv.z * w2.w + hv.w * w3.w;
        }
        // recurrent part: h2[t-1] . Whh1
        if (t > 0) {
            const float4* h2p = (const float4*)(g_H2 + (size_t)((t - 1) & 1) * (HD * 64));
#pragma unroll 4
            for (int k4 = 0; k4 < 192; k4++) {
                float4 hv = h2p[k4 * 64 + b];
                float4 w0 = Wsh[4608 + (k4 * 4 + 0) * 6 + jl];
                float4 w1 = Wsh[4608 + (k4 * 4 + 1) * 6 + jl];
                float4 w2 = Wsh[4608 + (k4 * 4 + 2) * 6 + jl];
                float4 w3 = Wsh[4608 + (k4 * 4 + 3) * 6 + jl];
                ai += hv.x * w0.x + hv.y * w1.x + hv.z * w2.x + hv.w * w3.x;
                af += hv.x * w0.y + hv.y * w1.y + hv.z * w2.y + hv.w * w3.y;
                ag += hv.x * w0.z + hv.y * w1.z + hv.z * w2.z + hv.w * w3.z;
                ao += hv.x * w0.w + hv.y * w1.w + hv.z * w2.w + hv.w * w3.w;
            }
        }
        float ig = sigmoidf_(ai);
        float fg = sigmoidf_(af);
        float gg = tanhf(ag);
        float og = sigmoidf_(ao);
        c = fg * c + ig * gg;
        float h = og * tanhf(c);

        g_H2[(size_t)(t & 1) * (HD * 64) + (size_t)(((j >> 2) * 64 + b) * 4 + (j & 3))] = h;
        grid_barrier();
    }
}

// ---------------------------------------------------------------------------
// fc: out[b] = 70 * ( sum_l softsign(h2_last . W1[l] + b1[l]) * W2[l] + b2[0] )
// One block per batch, one thread per LU unit.
// ---------------------------------------------------------------------------
__global__ void fc_kernel(const float* __restrict__ W1, const float* __restrict__ b1,
                          const float* __restrict__ W2, const float* __restrict__ b2,
                          float* __restrict__ out)
{
    const int b = blockIdx.x;
    const int l = threadIdx.x;

    const float4* h2p = (const float4*)(g_H2 + (size_t)1 * (HD * 64));  // t=255 -> parity 1
    const float4* w1p = (const float4*)(W1 + (size_t)l * HD);

    float acc = 0.0f;
#pragma unroll 4
    for (int k4 = 0; k4 < 192; k4++) {
        float4 hv = h2p[k4 * 64 + b];
        float4 wv = w1p[k4];
        acc += hv.x * wv.x + hv.y * wv.y + hv.z * wv.z + hv.w * wv.w;
    }
    float z = acc + b1[l];
    float s = z / (1.0f + fabsf(z));
    float p = s * W2[l];

    __shared__ float red[LUD];
    red[l] = p;
    __syncthreads();
    for (int off = LUD / 2; off > 0; off >>= 1) {
        if (l < off) red[l] += red[l + off];
        __syncthreads();
    }
    if (l == 0) out[b] = (red[0] + b2[0]) * 70.0f;
}

// ---------------------------------------------------------------------------
extern "C" void kernel_launch(void* const* d_in, const int* in_sizes, int n_in,
                              void* d_out, int out_size)
{
    const float* x    = (const float*)d_in[0];
    const float* Wih0 = (const float*)d_in[1];
    const float* Whh0 = (const float*)d_in[2];
    const float* bih0 = (const float*)d_in[3];
    const float* bhh0 = (const float*)d_in[4];
    const float* Wih1 = (const float*)d_in[5];
    const float* Whh1 = (const float*)d_in[6];
    const float* bih1 = (const float*)d_in[7];
    const float* bhh1 = (const float*)d_in[8];
    const float* W1   = (const float*)d_in[9];
    const float* b1   = (const float*)d_in[10];
    const float* W2   = (const float*)d_in[11];
    const float* b2   = (const float*)d_in[12];
    float* out = (float*)d_out;

    cudaFuncSetAttribute(lstm0_kernel, cudaFuncAttributeMaxDynamicSharedMemorySize, 768 * 24 * 4);
    cudaFuncSetAttribute(lstm1_kernel, cudaFuncAttributeMaxDynamicSharedMemorySize, 1536 * 24 * 4);

    proj0_kernel<<<dim3(48, 256), 256>>>(x, Wih0, bih0, bhh0);
    lstm0_kernel<<<NCTA, 384, 768 * 24 * 4>>>(Whh0);
    lstm1_kernel<<<NCTA, 384, 1536 * 24 * 4>>>(Wih1, Whh1, bih1, bhh1);
    fc_kernel<<<BSZ, LUD>>>(W1, b1, W2, b2, out);
}

// round 2
// speedup vs baseline: 1.4518x; 1.4518x over previous
#include <cuda_runtime.h>
#include <math.h>

// Problem constants
#define BSZ   64
#define TT    256
#define IND   64
#define HD    768
#define G4    3072      // 4*H
#define NCTA  128       // persistent grid size (<= 148 SMs -> all co-resident)
#define LUD   256

// Scratch (static device allocations are the sanctioned workaround)
__device__ __align__(16) float g_XG[(size_t)TT * G4 * BSZ];   // [t][gatecol][b]  (layer0, then reused for layer1)
__device__ __align__(16) float g_H1[(size_t)TT * HD * BSZ];   // [t][k>>2][b][k&3]
__device__ __align__(16) float g_H2[2 * HD * BSZ];            // double buffer, same interleave
__device__ unsigned long long g_bar = 0;                      // cumulative barrier counter

// ---------------------------------------------------------------------------
// Software grid barrier: cumulative-ticket scheme, safe across graph replays.
// ---------------------------------------------------------------------------
__device__ __forceinline__ void grid_barrier()
{
    __threadfence();          // release h stores
    __syncthreads();
    if (threadIdx.x == 0) {
        unsigned long long ticket = atomicAdd(&g_bar, 1ULL) + 1ULL;
        unsigned long long need = ((ticket + (NCTA - 1)) / NCTA) * NCTA;
        volatile unsigned long long* p = &g_bar;
        while (*p < need) { __nanosleep(40); }
    }
    __syncthreads();
    __threadfence();          // acquire
}

__device__ __forceinline__ float sigmoidf_(float x)
{
    return 1.0f / (1.0f + __expf(-x));
}

// ---------------------------------------------------------------------------
// proj0: g_XG[t][c][b] = sum_d (x[b][t][d]/1.5) * Wih0[c][d] + bih0[c] + bhh0[c]
// ---------------------------------------------------------------------------
__global__ void proj0_kernel(const float* __restrict__ x,
                             const float* __restrict__ Wih0,
                             const float* __restrict__ bih0,
                             const float* __restrict__ bhh0)
{
    __shared__ float4 Xs4[64 * 17];
    __shared__ float4 Ws4[64 * 17];
    float* Xs = (float*)Xs4;
    float* Ws = (float*)Ws4;

    const int t   = blockIdx.y;
    const int c0  = blockIdx.x * 64;
    const int tid = threadIdx.x;
    const float inv = 1.0f / 1.5f;

    for (int idx = tid; idx < 64 * 64; idx += 256) {
        int b = idx >> 6, d = idx & 63;
        Xs[b * 68 + d] = x[((b * TT) + t) * IND + d] * inv;
    }
    for (int idx = tid; idx < 64 * 64; idx += 256) {
        int c = idx >> 6, d = idx & 63;
        Ws[c * 68 + d] = Wih0[(c0 + c) * IND + d];
    }
    __syncthreads();

    const int b  = tid & 63;
    const int cw = tid >> 6;

    float acc[16];
#pragma unroll
    for (int m = 0; m < 16; m++) acc[m] = 0.0f;

#pragma unroll
    for (int d4 = 0; d4 < 16; d4++) {
        float4 xv = Xs4[b * 17 + d4];
#pragma unroll
        for (int m = 0; m < 16; m++) {
            float4 wv = Ws4[(cw + 4 * m) * 17 + d4];
            acc[m] += xv.x * wv.x + xv.y * wv.y + xv.z * wv.z + xv.w * wv.w;
        }
    }
#pragma unroll
    for (int m = 0; m < 16; m++) {
        int c = c0 + cw + 4 * m;
        g_XG[((size_t)t * G4 + c) * 64 + b] = acc[m] + bih0[c] + bhh0[c];
    }
}

// ---------------------------------------------------------------------------
// proj1: layer-1 input projection, parallel over all (t, c):
//   g_XG[t][c][b] = sum_k H1[t][k][b] * Wih1[c][k] + bih1[c] + bhh1[c]
// K=768, chunked by 64. H1 is [t][k4][b][4] interleaved (float4 over k).
// ---------------------------------------------------------------------------
__global__ void proj1_kernel(const float* __restrict__ Wih1,
                             const float* __restrict__ bih1,
                             const float* __restrict__ bhh1)
{
    __shared__ float4 Hs4[64 * 17];   // [b][k4]
    __shared__ float4 Ws4[64 * 17];   // [c][k4]

    const int t   = blockIdx.y;
    const int c0  = blockIdx.x * 64;
    const int tid = threadIdx.x;
    const int b   = tid & 63;
    const int cw  = tid >> 6;

    const float4* h4 = (const float4*)g_H1 + (size_t)t * (HD * 16); // 12288 f4/t

    float acc[16];
#pragma unroll
    for (int m = 0; m < 16; m++) acc[m] = 0.0f;

    for (int k0 = 0; k0 < 12; k0++) {       // 12 chunks of 64 k
        __syncthreads();
        for (int idx = tid; idx < 1024; idx += 256) {
            int bb = idx & 63, k4i = idx >> 6;
            Hs4[bb * 17 + k4i] = h4[(k0 * 16 + k4i) * 64 + bb];   // coalesced over bb
        }
        for (int idx = tid; idx < 1024; idx += 256) {
            int cc = idx >> 4, kc4 = idx & 15;
            Ws4[cc * 17 + kc4] =
                *(const float4*)(Wih1 + (size_t)(c0 + cc) * HD + k0 * 64 + kc4 * 4);
        }
        __syncthreads();
#pragma unroll
        for (int d4 = 0; d4 < 16; d4++) {
            float4 xv = Hs4[b * 17 + d4];
#pragma unroll
            for (int m = 0; m < 16; m++) {
                float4 wv = Ws4[(cw + 4 * m) * 17 + d4];
                acc[m] += xv.x * wv.x + xv.y * wv.y + xv.z * wv.z + xv.w * wv.w;
            }
        }
    }
#pragma unroll
    for (int m = 0; m < 16; m++) {
        int c = c0 + cw + 4 * m;
        g_XG[((size_t)t * G4 + c) * 64 + b] = acc[m] + bih1[c] + bhh1[c];
    }
}

// ---------------------------------------------------------------------------
// Recurrence kernel body (shared by both layers):
// CTA owns 6 h-cols; per step, stage h[t-1] into smem (2 chunks of 384 k),
// then FFMA against weights held in smem. h exchanged via L2 + grid barrier.
// ---------------------------------------------------------------------------
__global__ void __launch_bounds__(384, 1)
lstm0_kernel(const float* __restrict__ Whh0)
{
    extern __shared__ float4 sm[];
    float4* Wsh = sm;            // 4608 f4 (73728 B): [k][jj][gate]
    float4* Hs  = sm + 4608;     // 6144 f4 (98304 B): [k4][b]
    float*  Wsf = (float*)Wsh;

    const int tid = threadIdx.x;
    const int jl  = tid / 64;
    const int b   = tid & 63;
    const int j   = blockIdx.x * 6 + jl;

    for (int idx = tid; idx < 768 * 24; idx += 384) {
        int k  = idx / 24;
        int r  = idx % 24;
        int jj = r >> 2;
        int gi = r & 3;
        Wsf[idx] = Whh0[(gi * 768 + blockIdx.x * 6 + jj) * 768 + k];
    }
    __syncthreads();

    float c = 0.0f;
    for (int t = 0; t < TT; t++) {
        int base = (t * G4 + j) * 64 + b;
        float ai = g_XG[base];
        float af = g_XG[base + 768 * 64];
        float ag = g_XG[base + 1536 * 64];
        float ao = g_XG[base + 2304 * 64];

        if (t > 0) {
            const float4* h4 = (const float4*)g_H1 + (size_t)(t - 1) * (HD * 16);
#pragma unroll
            for (int ch = 0; ch < 2; ch++) {
                __syncthreads();
#pragma unroll
                for (int i = 0; i < 16; i++) {
                    int idx = tid + i * 384;
                    Hs[idx] = __ldcg(&h4[ch * 6144 + idx]);
                }
                __syncthreads();
#pragma unroll 8
                for (int k4 = 0; k4 < 96; k4++) {
                    float4 hv = Hs[k4 * 64 + b];
                    int wb = ((ch * 96 + k4) * 4) * 6 + jl;
                    float4 w0 = Wsh[wb];
                    float4 w1 = Wsh[wb + 6];
                    float4 w2 = Wsh[wb + 12];
                    float4 w3 = Wsh[wb + 18];
                    ai += hv.x * w0.x + hv.y * w1.x + hv.z * w2.x + hv.w * w3.x;
                    af += hv.x * w0.y + hv.y * w1.y + hv.z * w2.y + hv.w * w3.y;
                    ag += hv.x * w0.z + hv.y * w1.z + hv.z * w2.z + hv.w * w3.z;
                    ao += hv.x * w0.w + hv.y * w1.w + hv.z * w2.w + hv.w * w3.w;
                }
            }
        }
        float ig = sigmoidf_(ai);
        float fg = sigmoidf_(af);
        float gg = tanhf(ag);
        float og = sigmoidf_(ao);
        c = fg * c + ig * gg;
        float h = og * tanhf(c);

        g_H1[(size_t)t * (HD * 64) + (size_t)(((j >> 2) * 64 + b) * 4 + (j & 3))] = h;
        grid_barrier();
    }
}

__global__ void __launch_bounds__(384, 1)
lstm1_kernel(const float* __restrict__ Whh1)
{
    extern __shared__ float4 sm[];
    float4* Wsh = sm;
    float4* Hs  = sm + 4608;
    float*  Wsf = (float*)Wsh;

    const int tid = threadIdx.x;
    const int jl  = tid / 64;
    const int b   = tid & 63;
    const int j   = blockIdx.x * 6 + jl;

    for (int idx = tid; idx < 768 * 24; idx += 384) {
        int k  = idx / 24;
        int r  = idx % 24;
        int jj = r >> 2;
        int gi = r & 3;
        Wsf[idx] = Whh1[(gi * 768 + blockIdx.x * 6 + jj) * 768 + k];
    }
    __syncthreads();

    float c = 0.0f;
    for (int t = 0; t < TT; t++) {
        int base = (t * G4 + j) * 64 + b;
        float ai = g_XG[base];
        float af = g_XG[base + 768 * 64];
        float ag = g_XG[base + 1536 * 64];
        float ao = g_XG[base + 2304 * 64];

        if (t > 0) {
            const float4* h4 = (const float4*)g_H2 + (size_t)((t - 1) & 1) * (HD * 16);
#pragma unroll
            for (int ch = 0; ch < 2; ch++) {
                __syncthreads();
#pragma unroll
                for (int i = 0; i < 16; i++) {
                    int idx = tid + i * 384;
                    Hs[idx] = __ldcg(&h4[ch * 6144 + idx]);
                }
                __syncthreads();
#pragma unroll 8
                for (int k4 = 0; k4 < 96; k4++) {
                    float4 hv = Hs[k4 * 64 + b];
                    int wb = ((ch * 96 + k4) * 4) * 6 + jl;
                    float4 w0 = Wsh[wb];
                    float4 w1 = Wsh[wb + 6];
                    float4 w2 = Wsh[wb + 12];
                    float4 w3 = Wsh[wb + 18];
                    ai += hv.x * w0.x + hv.y * w1.x + hv.z * w2.x + hv.w * w3.x;
                    af += hv.x * w0.y + hv.y * w1.y + hv.z * w2.y + hv.w * w3.y;
                    ag += hv.x * w0.z + hv.y * w1.z + hv.z * w2.z + hv.w * w3.z;
                    ao += hv.x * w0.w + hv.y * w1.w + hv.z * w2.w + hv.w * w3.w;
                }
            }
        }
        float ig = sigmoidf_(ai);
        float fg = sigmoidf_(af);
        float gg = tanhf(ag);
        float og = sigmoidf_(ao);
        c = fg * c + ig * gg;
        float h = og * tanhf(c);

        g_H2[(size_t)(t & 1) * (HD * 64) + (size_t)(((j >> 2) * 64 + b) * 4 + (j & 3))] = h;
        grid_barrier();
    }
}

// ---------------------------------------------------------------------------
// fc head
// ---------------------------------------------------------------------------
__global__ void fc_kernel(const float* __restrict__ W1, const float* __restrict__ b1,
                          const float* __restrict__ W2, const float* __restrict__ b2,
                          float* __restrict__ out)
{
    const int b = blockIdx.x;
    const int l = threadIdx.x;

    const float4* h2p = (const float4*)(g_H2 + (size_t)1 * (HD * 64));  // t=255 -> parity 1
    const float4* w1p = (const float4*)(W1 + (size_t)l * HD);

    float acc = 0.0f;
#pragma unroll 4
    for (int k4 = 0; k4 < 192; k4++) {
        float4 hv = h2p[k4 * 64 + b];
        float4 wv = w1p[k4];
        acc += hv.x * wv.x + hv.y * wv.y + hv.z * wv.z + hv.w * wv.w;
    }
    float z = acc + b1[l];
    float s = z / (1.0f + fabsf(z));
    float p = s * W2[l];

    __shared__ float red[LUD];
    red[l] = p;
    __syncthreads();
    for (int off = LUD / 2; off > 0; off >>= 1) {
        if (l < off) red[l] += red[l + off];
        __syncthreads();
    }
    if (l == 0) out[b] = (red[0] + b2[0]) * 70.0f;
}

// ---------------------------------------------------------------------------
extern "C" void kernel_launch(void* const* d_in, const int* in_sizes, int n_in,
                              void* d_out, int out_size)
{
    const float* x    = (const float*)d_in[0];
    const float* Wih0 = (const float*)d_in[1];
    const float* Whh0 = (const float*)d_in[2];
    const float* bih0 = (const float*)d_in[3];
    const float* bhh0 = (const float*)d_in[4];
    const float* Wih1 = (const float*)d_in[5];
    const float* Whh1 = (const float*)d_in[6];
    const float* bih1 = (const float*)d_in[7];
    const float* bhh1 = (const float*)d_in[8];
    const float* W1   = (const float*)d_in[9];
    const float* b1   = (const float*)d_in[10];
    const float* W2   = (const float*)d_in[11];
    const float* b2   = (const float*)d_in[12];
    float* out = (float*)d_out;

    const int lstm_smem = (4608 + 6144) * 16;   // 172032 B
    cudaFuncSetAttribute(lstm0_kernel, cudaFuncAttributeMaxDynamicSharedMemorySize, lstm_smem);
    cudaFuncSetAttribute(lstm1_kernel, cudaFuncAttributeMaxDynamicSharedMemorySize, lstm_smem);

    proj0_kernel<<<dim3(48, 256), 256>>>(x, Wih0, bih0, bhh0);
    lstm0_kernel<<<NCTA, 384, lstm_smem>>>(Whh0);
    proj1_kernel<<<dim3(48, 256), 256>>>(Wih1, bih1, bhh1);
    lstm1_kernel<<<NCTA, 384, lstm_smem>>>(Whh1);
    fc_kernel<<<BSZ, LUD>>>(W1, b1, W2, b2, out);
}